// round 2
// baseline (speedup 1.0000x reference)
#include <cuda_runtime.h>
#include <cstdint>
#include <math.h>

#define DEVI __device__ __forceinline__

static constexpr int BN = 16384, FAN = 16, BE = BN * FAN, EMB = 128, HID = 256;

// device scratch (no allocations allowed)
__device__ __align__(16) float g_relb2[16 * HID];
__device__ __align__(16) float g_neigh[BN * HID];

DEVI uint32_t smaddr(const void* p) {
    uint32_t a;
    asm("{ .reg .u64 t; cvta.to.shared.u64 t, %1; cvt.u32.u64 %0, t; }" : "=r"(a) : "l"(p));
    return a;
}
DEVI void cpa16(uint32_t d, const void* s) {
    asm volatile("cp.async.ca.shared.global [%0], [%1], 16;" :: "r"(d), "l"(s));
}
#define CP_COMMIT() asm volatile("cp.async.commit_group;")
#define CP_WAIT(n)  asm volatile("cp.async.wait_group %0;" :: "n"(n))

DEVI uint32_t tf32u(float x) {
    uint32_t u;
    asm("cvt.rna.tf32.f32 %0, %1;" : "=r"(u) : "f"(x));
    return u;
}
DEVI void mma8(float* c, const uint32_t* a, uint32_t b0, uint32_t b1) {
    asm volatile(
        "mma.sync.aligned.m16n8k8.row.col.f32.tf32.tf32.f32 "
        "{%0,%1,%2,%3}, {%4,%5,%6,%7}, {%8,%9}, {%0,%1,%2,%3};"
        : "+f"(c[0]), "+f"(c[1]), "+f"(c[2]), "+f"(c[3])
        : "r"(a[0]), "r"(a[1]), "r"(a[2]), "r"(a[3]), "r"(b0), "r"(b1));
}

static constexpr int LD  = 36;        // smem row stride in floats (conflict-free: (4g+t)%32 distinct)
static constexpr int A_F = 128 * LD;  // 4608 floats per A buffer
static constexpr int B_F = 256 * LD;  // 9216 floats per B buffer

// One K=32 chunk of warp-tiled MMA. CTA: M=128,N=256; 16 warps, warp tile 32x64.
DEVI void mma_chunk(const float* As, const float* Bs, int wm, int wn, int g, int t,
                    float (&acc)[2][8][4]) {
#pragma unroll
    for (int ks = 0; ks < 4; ks++) {
        const int k0 = ks * 8;
        uint32_t a[2][4];
#pragma unroll
        for (int mt = 0; mt < 2; mt++) {
            const float* r0 = As + (wm * 32 + mt * 16 + g) * LD + k0;
            const float* r8 = r0 + 8 * LD;
            a[mt][0] = tf32u(r0[t]);     a[mt][1] = tf32u(r8[t]);
            a[mt][2] = tf32u(r0[t + 4]); a[mt][3] = tf32u(r8[t + 4]);
        }
#pragma unroll
        for (int nt = 0; nt < 8; nt++) {
            const float* br = Bs + (wn * 64 + nt * 8 + g) * LD + k0;
            uint32_t b0 = tf32u(br[t]), b1 = tf32u(br[t + 4]);
            mma8(acc[0][nt], a[0], b0, b1);
            mma8(acc[1][nt], a[1], b0, b1);
        }
    }
}

// ---------------- kernel 1: relb2[r][j] = b2[j] + edge_emb[r] . edge_lin_w[j] ----------------
__global__ void k_relproj(const float* __restrict__ eemb, const float* __restrict__ We,
                          const float* __restrict__ b2) {
    int r = blockIdx.x, j = threadIdx.x;
    const float4* e = (const float4*)(eemb + r * EMB);
    const float4* w = (const float4*)(We + (long)j * EMB);
    float acc = b2[j];
#pragma unroll
    for (int k = 0; k < EMB / 4; k++) {
        float4 a = e[k], b = w[k];
        acc += a.x * b.x + a.y * b.y + a.z * b.z + a.w * b.w;
    }
    g_relb2[r * HID + j] = acc;
}

// ---------------- kernel 2: event GEMM [BE,512]x[512,256] -> mask/relu -> mean -> g_neigh ----------------
extern __shared__ float smf[];

__global__ void __launch_bounds__(512) k_events(
    const int* __restrict__ nbr_ev, const int* __restrict__ ev_st,
    const int* __restrict__ ev_dt, const int* __restrict__ ev_et,
    const int* __restrict__ ev_sid, const int* __restrict__ ev_did,
    const int* __restrict__ ev_ts, const float* __restrict__ ev_w,
    const float* __restrict__ emb0, const float* __restrict__ emb1,
    const float* __restrict__ Ws, const float* __restrict__ Wd,
    const float* __restrict__ W2, const float* __restrict__ w1,
    const float* __restrict__ b1v)
{
    float* As0 = smf;            float* As1 = smf + A_F;
    float* Bs0 = smf + 2 * A_F;  float* Bs1 = smf + 2 * A_F + B_F;
    float* meta = smf + 2 * A_F + 2 * B_F;
    const float** srcP = (const float**)meta;            // 128 ptrs
    const float** dstP = (const float**)(meta + 256);    // 128 ptrs
    int*   relA = (int*)(meta + 512);
    float* vmA  = meta + 640;
    float* tsA  = meta + 768;
    float* wlA  = meta + 896;
    float* rb   = meta + 1024;                            // 16x256
    float2* w1s = (float2*)(meta + 5120);                 // 256
    float* b1s  = meta + 5632;                            // 256

    const int tid = threadIdx.x;
    const int wid = tid >> 5, lane = tid & 31;
    const int wm = wid >> 2, wn = wid & 3;
    const int g = lane >> 2, t = lane & 3;

    // ---- stage per-event metadata ----
    if (tid < 128) {
        int e   = blockIdx.x * 128 + tid;
        int raw = nbr_ev[e];
        int v   = raw >= 0;
        int ev  = v ? raw : 0;
        long sid = ev_sid[ev], did = ev_did[ev];
        srcP[tid] = (ev_st[ev] == 0 ? emb0 : emb1) + sid * EMB;
        dstP[tid] = (ev_dt[ev] == 0 ? emb0 : emb1) + did * EMB;
        relA[tid] = ev_et[ev];
        vmA[tid]  = v ? 1.0f : 0.0f;
        tsA[tid]  = (float)ev_ts[ev] / 1000000.0f;
        wlA[tid]  = log1pf(ev_w[ev]);
    }
#pragma unroll
    for (int i = 0; i < 8; i++) rb[tid + i * 512] = g_relb2[tid + i * 512];
    if (tid < 256) {
        w1s[tid] = make_float2(w1[tid * 2], w1[tid * 2 + 1]);
        b1s[tid] = b1v[tid];
    }
    __syncthreads();

    const uint32_t aU[2] = {smaddr(As0), smaddr(As1)};
    const uint32_t bU[2] = {smaddr(Bs0), smaddr(Bs1)};
    float* Asp[2] = {As0, As1};
    float* Bsp[2] = {Bs0, Bs1};

    auto load_chunk = [&](int kc, int buf) {
        // B chunk: 256 rows x 32 floats (4 cp.async per thread)
#pragma unroll
        for (int i = 0; i < 4; i++) {
            int task = tid + i * 512, n = task >> 3, seg = task & 7;
            const float* p;
            if (kc < 4)      p = Ws + n * 128 + kc * 32;
            else if (kc < 8) p = Wd + n * 128 + (kc - 4) * 32;
            else             p = W2 + n * 256 + (kc - 8) * 32;
            cpa16(bU[buf] + (n * LD + seg * 4) * 4, p + seg * 4);
        }
        if (kc < 8) {  // A chunk: gathered src/dst embeddings (2 cp.async per thread)
#pragma unroll
            for (int i = 0; i < 2; i++) {
                int task = tid + i * 512, row = task >> 3, seg = task & 7;
                const float* p = (kc < 4 ? srcP[row] : dstP[row]) + (kc & 3) * 32;
                cpa16(aU[buf] + (row * LD + seg * 4) * 4, p + seg * 4);
            }
        } else {       // A chunk: compute a1 = relu(feat @ W1^T + b1) on the fly
            float* A = Asp[buf];
#pragma unroll
            for (int i = 0; i < 8; i++) {
                int task = tid + i * 512, e = task >> 5, c = task & 31;
                int j = (kc - 8) * 32 + c;
                float2 wv = w1s[j];
                A[e * LD + c] = fmaxf(tsA[e] * wv.x + wlA[e] * wv.y + b1s[j], 0.0f);
            }
        }
    };

    float acc[2][8][4];
#pragma unroll
    for (int mt = 0; mt < 2; mt++)
#pragma unroll
        for (int nt = 0; nt < 8; nt++)
#pragma unroll
            for (int r = 0; r < 4; r++) acc[mt][nt][r] = 0.0f;

    load_chunk(0, 0);
    CP_COMMIT();
    for (int kc = 0; kc < 16; kc++) {
        int cur = kc & 1;
        if (kc < 15) { load_chunk(kc + 1, cur ^ 1); CP_COMMIT(); CP_WAIT(1); }
        else         { CP_WAIT(0); }
        __syncthreads();
        mma_chunk(Asp[cur], Bsp[cur], wm, wn, g, t, acc);
        __syncthreads();
    }

    // ---- epilogue: +relb2[rel], relu, mask, mean over each 16-row node group ----
#pragma unroll
    for (int mt = 0; mt < 2; mt++) {
        int mrow0 = wm * 32 + mt * 16;
        int eg = mrow0 + g, eg8 = eg + 8;
        float vg = vmA[eg], vg8 = vmA[eg8];
        const float* rbg  = rb + relA[eg] * 256;
        const float* rbg8 = rb + relA[eg8] * 256;
        int node = blockIdx.x * 8 + wm * 2 + mt;
#pragma unroll
        for (int nt = 0; nt < 8; nt++) {
            int col = wn * 64 + nt * 8 + t * 2;
            float s0 = fmaxf(acc[mt][nt][0] + rbg[col], 0.0f) * vg
                     + fmaxf(acc[mt][nt][2] + rbg8[col], 0.0f) * vg8;
            float s1 = fmaxf(acc[mt][nt][1] + rbg[col + 1], 0.0f) * vg
                     + fmaxf(acc[mt][nt][3] + rbg8[col + 1], 0.0f) * vg8;
            s0 += __shfl_xor_sync(0xFFFFFFFFu, s0, 4);
            s0 += __shfl_xor_sync(0xFFFFFFFFu, s0, 8);
            s0 += __shfl_xor_sync(0xFFFFFFFFu, s0, 16);
            s1 += __shfl_xor_sync(0xFFFFFFFFu, s1, 4);
            s1 += __shfl_xor_sync(0xFFFFFFFFu, s1, 8);
            s1 += __shfl_xor_sync(0xFFFFFFFFu, s1, 16);
            if (g == 0)
                *(float2*)(g_neigh + node * 256 + col) =
                    make_float2(s0 * 0.0625f, s1 * 0.0625f);
        }
    }
}

// ---------------- kernel 3: out = relu(self_e @ Wself^T + neigh @ Wneigh^T) ----------------
__global__ void __launch_bounds__(512) k_final(
    const int* __restrict__ node_ids, const float* __restrict__ emb0,
    const float* __restrict__ Wself, const float* __restrict__ Wneigh,
    float* __restrict__ out)
{
    float* As0 = smf;            float* As1 = smf + A_F;
    float* Bs0 = smf + 2 * A_F;  float* Bs1 = smf + 2 * A_F + B_F;
    float* meta = smf + 2 * A_F + 2 * B_F;
    const float** selfP = (const float**)meta;  // 128 ptrs

    const int tid = threadIdx.x;
    const int wid = tid >> 5, lane = tid & 31;
    const int wm = wid >> 2, wn = wid & 3;
    const int g = lane >> 2, t = lane & 3;

    if (tid < 128) {
        long nid = node_ids[blockIdx.x * 128 + tid];
        selfP[tid] = emb0 + nid * EMB;
    }
    __syncthreads();

    const uint32_t aU[2] = {smaddr(As0), smaddr(As1)};
    const uint32_t bU[2] = {smaddr(Bs0), smaddr(Bs1)};
    float* Asp[2] = {As0, As1};
    float* Bsp[2] = {Bs0, Bs1};

    auto load_chunk = [&](int kc, int buf) {
#pragma unroll
        for (int i = 0; i < 4; i++) {
            int task = tid + i * 512, n = task >> 3, seg = task & 7;
            const float* p = (kc < 4) ? (Wself + n * 128 + kc * 32)
                                      : (Wneigh + n * 256 + (kc - 4) * 32);
            cpa16(bU[buf] + (n * LD + seg * 4) * 4, p + seg * 4);
        }
#pragma unroll
        for (int i = 0; i < 2; i++) {
            int task = tid + i * 512, row = task >> 3, seg = task & 7;
            const float* p;
            if (kc < 4) p = selfP[row] + kc * 32;
            else        p = g_neigh + (long)(blockIdx.x * 128 + row) * 256 + (kc - 4) * 32;
            cpa16(aU[buf] + (row * LD + seg * 4) * 4, p + seg * 4);
        }
    };

    float acc[2][8][4];
#pragma unroll
    for (int mt = 0; mt < 2; mt++)
#pragma unroll
        for (int nt = 0; nt < 8; nt++)
#pragma unroll
            for (int r = 0; r < 4; r++) acc[mt][nt][r] = 0.0f;

    load_chunk(0, 0);
    CP_COMMIT();
    for (int kc = 0; kc < 12; kc++) {
        int cur = kc & 1;
        if (kc < 11) { load_chunk(kc + 1, cur ^ 1); CP_COMMIT(); CP_WAIT(1); }
        else         { CP_WAIT(0); }
        __syncthreads();
        mma_chunk(Asp[cur], Bsp[cur], wm, wn, g, t, acc);
        __syncthreads();
    }

#pragma unroll
    for (int mt = 0; mt < 2; mt++) {
        int row0 = blockIdx.x * 128 + wm * 32 + mt * 16;
#pragma unroll
        for (int nt = 0; nt < 8; nt++) {
            int col = wn * 64 + nt * 8 + t * 2;
            *(float2*)(out + (long)(row0 + g) * 256 + col) =
                make_float2(fmaxf(acc[mt][nt][0], 0.0f), fmaxf(acc[mt][nt][1], 0.0f));
            *(float2*)(out + (long)(row0 + g + 8) * 256 + col) =
                make_float2(fmaxf(acc[mt][nt][2], 0.0f), fmaxf(acc[mt][nt][3], 0.0f));
        }
    }
}

static constexpr int SMEM2 = (2 * A_F + 2 * B_F + 5888) * 4;  // 134144 B
static constexpr int SMEM3 = (2 * A_F + 2 * B_F + 256) * 4;   // 111616 B

extern "C" void kernel_launch(void* const* d_in, const int* in_sizes, int n_in,
                              void* d_out, int out_size) {
    const int*   node_ids = (const int*)d_in[0];
    const int*   nbr_ev   = (const int*)d_in[1];
    const int*   ev_st    = (const int*)d_in[2];
    const int*   ev_dt    = (const int*)d_in[3];
    const int*   ev_et    = (const int*)d_in[4];
    const int*   ev_sid   = (const int*)d_in[5];
    const int*   ev_did   = (const int*)d_in[6];
    const int*   ev_ts    = (const int*)d_in[7];
    const float* ev_w     = (const float*)d_in[8];
    const float* emb0     = (const float*)d_in[9];
    const float* emb1     = (const float*)d_in[10];
    const float* edge_emb = (const float*)d_in[11];
    const float* edge_lin = (const float*)d_in[12];
    const float* mlp_w1   = (const float*)d_in[13];
    const float* mlp_b1   = (const float*)d_in[14];
    const float* mlp_w2   = (const float*)d_in[15];
    const float* mlp_b2   = (const float*)d_in[16];
    const float* ev_src_w = (const float*)d_in[17];
    const float* ev_dst_w = (const float*)d_in[18];
    const float* self_w   = (const float*)d_in[19];
    const float* neigh_w  = (const float*)d_in[20];
    float* out = (float*)d_out;

    cudaFuncSetAttribute(k_events, cudaFuncAttributeMaxDynamicSharedMemorySize, SMEM2);
    cudaFuncSetAttribute(k_final,  cudaFuncAttributeMaxDynamicSharedMemorySize, SMEM3);

    k_relproj<<<16, 256>>>(edge_emb, edge_lin, mlp_b2);
    k_events<<<BE / 128, 512, SMEM2>>>(nbr_ev, ev_st, ev_dt, ev_et, ev_sid, ev_did,
                                       ev_ts, ev_w, emb0, emb1,
                                       ev_src_w, ev_dst_w, mlp_w2, mlp_w1, mlp_b1);
    k_final<<<BN / 128, 512, SMEM3>>>(node_ids, emb0, self_w, neigh_w, out);
}

// round 3
// speedup vs baseline: 1.1264x; 1.1264x over previous
#include <cuda_runtime.h>
#include <cstdint>
#include <math.h>

#define DEVI __device__ __forceinline__

static constexpr int BN = 16384, FAN = 16, BE = BN * FAN, EMB = 128, HID = 256;

// ---- device scratch (static; no allocations allowed) ----
__device__ __align__(16) float g_relb2[16 * HID];
__device__ __align__(16) float g_neigh[BN * HID];
__device__ __align__(16) float g_Bw [16 * 256 * 32];  // k_events B: tf32, permuted+swizzled smem image
__device__ __align__(16) float g_Bw2[12 * 256 * 32];  // k_final  B: same

DEVI uint32_t smaddr(const void* p) {
    uint32_t a;
    asm("{ .reg .u64 t; cvta.to.shared.u64 t, %1; cvt.u32.u64 %0, t; }" : "=r"(a) : "l"(p));
    return a;
}
DEVI void cpa16(uint32_t d, const void* s) {
    asm volatile("cp.async.ca.shared.global [%0], [%1], 16;" :: "r"(d), "l"(s));
}
#define CP_COMMIT() asm volatile("cp.async.commit_group;")
#define CP_WAIT(n)  asm volatile("cp.async.wait_group %0;" :: "n"(n))

DEVI uint32_t tf32u(float x) {
    uint32_t u;
    asm("cvt.rna.tf32.f32 %0, %1;" : "=r"(u) : "f"(x));
    return u;
}
DEVI void lds64(uint32_t& x, uint32_t& y, uint32_t a) {
    asm volatile("ld.shared.v2.b32 {%0,%1}, [%2];" : "=r"(x), "=r"(y) : "r"(a));
}
DEVI void mma8(float* c, const uint32_t* a, uint32_t b0, uint32_t b1) {
    asm volatile(
        "mma.sync.aligned.m16n8k8.row.col.f32.tf32.tf32.f32 "
        "{%0,%1,%2,%3}, {%4,%5,%6,%7}, {%8,%9}, {%0,%1,%2,%3};"
        : "+f"(c[0]), "+f"(c[1]), "+f"(c[2]), "+f"(c[3])
        : "r"(a[0]), "r"(a[1]), "r"(a[2]), "r"(a[3]), "r"(b0), "r"(b1));
}

static constexpr int LD   = 36;        // A smem row stride (floats), padded
static constexpr int A_F  = 128 * LD;  // 4608 floats / A stage
static constexpr int B2_F = 256 * 32;  // 8192 floats / B stage (dense 128B rows)

// ---- B staging: logical W[r][k] (k within 32-chunk) -> smem-image position ----
// pair-permute within each k8 group: j -> p = 2*(j&3)+(j>>2)  (puts k=t,t+4 adjacent)
// XOR-swizzle 16B chunks: c -> c ^ ((r&3)<<1)                 (conflict-free phases)
DEVI void stash(float* dst, int r, int k, float v) {
    int kg = k >> 3, j = k & 7;
    int pos = kg * 8 + 2 * (j & 3) + (j >> 2);
    int cc  = (pos >> 2) ^ ((r & 3) << 1);
    dst[r * 32 + cc * 4 + (pos & 3)] = __uint_as_float(tf32u(v));
}

// ---- one K=32 chunk of warp-tiled MMA; CTA 128x256, 16 warps, warp tile 32x64 ----
DEVI void mma_chunk(const float* As, uint32_t bB, int wm, int wn, int g, int t,
                    float (&acc)[2][8][4]) {
    const uint32_t sw = (uint32_t)((g & 3) << 1);
    uint32_t nbase[8];
#pragma unroll
    for (int nt = 0; nt < 8; nt++)
        nbase[nt] = bB + (uint32_t)((wn * 64 + nt * 8 + g) * 128) + ((t & 1) << 3);
#pragma unroll
    for (int ks = 0; ks < 4; ks++) {
        uint32_t a[2][4];
#pragma unroll
        for (int mt = 0; mt < 2; mt++) {
            const float* r0 = As + (wm * 32 + mt * 16 + g) * LD + ks * 8;
            const float* r8 = r0 + 8 * LD;
            a[mt][0] = tf32u(r0[t]);     a[mt][1] = tf32u(r8[t]);
            a[mt][2] = tf32u(r0[t + 4]); a[mt][3] = tf32u(r8[t + 4]);
        }
        const uint32_t cc = (((uint32_t)(ks * 2 + (t >> 1))) ^ sw) << 4;
#pragma unroll
        for (int nt = 0; nt < 8; nt++) {
            uint32_t b0, b1;
            lds64(b0, b1, nbase[nt] + cc);
            mma8(acc[0][nt], a[0], b0, b1);
            mma8(acc[1][nt], a[1], b0, b1);
        }
    }
}

// ---------------- kernel 0: stage weights (tf32 + permute + swizzle) ----------------
__global__ void k_prep(const float* __restrict__ Ws, const float* __restrict__ Wd,
                       const float* __restrict__ W2, const float* __restrict__ Wself,
                       const float* __restrict__ Wneigh) {
    int flat = blockIdx.x * 256 + threadIdx.x;
    if (flat < 16 * 8192) {
        int chunk = flat >> 13, r = (flat >> 5) & 255, k = flat & 31;
        float v;
        if (chunk < 4)      v = Ws[r * 128 + chunk * 32 + k];
        else if (chunk < 8) v = Wd[r * 128 + (chunk - 4) * 32 + k];
        else                v = W2[r * 256 + (chunk - 8) * 32 + k];
        stash(g_Bw + chunk * 8192, r, k, v);
    } else {
        int f = flat - 16 * 8192;
        int chunk = f >> 13, r = (f >> 5) & 255, k = f & 31;
        float v = (chunk < 4) ? Wself[r * 128 + chunk * 32 + k]
                              : Wneigh[r * 256 + (chunk - 4) * 32 + k];
        stash(g_Bw2 + chunk * 8192, r, k, v);
    }
}

// ---------------- kernel 1: relb2[r][j] = b2[j] + edge_emb[r] . edge_lin_w[j] ----------------
__global__ void k_relproj(const float* __restrict__ eemb, const float* __restrict__ We,
                          const float* __restrict__ b2) {
    int r = blockIdx.x, j = threadIdx.x;
    const float4* e = (const float4*)(eemb + r * EMB);
    const float4* w = (const float4*)(We + (long)j * EMB);
    float acc = b2[j];
#pragma unroll
    for (int k = 0; k < EMB / 4; k++) {
        float4 a = e[k], b = w[k];
        acc += a.x * b.x + a.y * b.y + a.z * b.z + a.w * b.w;
    }
    g_relb2[r * HID + j] = acc;
}

// ---------------- kernel 2: event GEMM [BE,512]x[512,256] -> mask/relu -> mean ----------------
extern __shared__ float smf[];

__global__ void __launch_bounds__(512) k_events(
    const int* __restrict__ nbr_ev, const int* __restrict__ ev_st,
    const int* __restrict__ ev_dt, const int* __restrict__ ev_et,
    const int* __restrict__ ev_sid, const int* __restrict__ ev_did,
    const int* __restrict__ ev_ts, const float* __restrict__ ev_w,
    const float* __restrict__ emb0, const float* __restrict__ emb1,
    const float* __restrict__ w1, const float* __restrict__ b1v)
{
    float* Bsb  = smf;                       // 3 x B2_F
    float* Asb  = smf + 3 * B2_F;            // 3 x A_F
    float* meta = smf + 3 * B2_F + 3 * A_F;
    const float** srcP = (const float**)meta;           // 128 ptrs (256 f)
    const float** dstP = (const float**)(meta + 256);   // 128 ptrs
    int*   relA = (int*)(meta + 512);
    float* vmA  = meta + 640;
    float* tsA  = meta + 768;
    float* wlA  = meta + 896;
    float* rb   = meta + 1024;                          // 16x256
    float2* w1s = (float2*)(meta + 5120);               // 256
    float* b1s  = meta + 5632;                          // 256

    const int tid = threadIdx.x;
    const int wid = tid >> 5, lane = tid & 31;
    const int wm = wid >> 2, wn = wid & 3;
    const int g = lane >> 2, t = lane & 3;

    if (tid < 128) {
        int e   = blockIdx.x * 128 + tid;
        int raw = nbr_ev[e];
        int v   = raw >= 0;
        int ev  = v ? raw : 0;
        long sid = ev_sid[ev], did = ev_did[ev];
        srcP[tid] = (ev_st[ev] == 0 ? emb0 : emb1) + sid * EMB;
        dstP[tid] = (ev_dt[ev] == 0 ? emb0 : emb1) + did * EMB;
        relA[tid] = ev_et[ev];
        vmA[tid]  = v ? 1.0f : 0.0f;
        tsA[tid]  = (float)ev_ts[ev] / 1000000.0f;
        wlA[tid]  = log1pf(ev_w[ev]);
    }
#pragma unroll
    for (int i = 0; i < 8; i++) rb[tid + i * 512] = g_relb2[tid + i * 512];
    if (tid < 256) {
        w1s[tid] = make_float2(w1[tid * 2], w1[tid * 2 + 1]);
        b1s[tid] = b1v[tid];
    }
    __syncthreads();

    uint32_t bU[3]; float* Asp[3];
#pragma unroll
    for (int s = 0; s < 3; s++) {
        bU[s]  = smaddr(Bsb + s * B2_F);
        Asp[s] = Asb + s * A_F;
    }
    uint32_t aU[3];
#pragma unroll
    for (int s = 0; s < 3; s++) aU[s] = smaddr(Asp[s]);

    auto load_chunk = [&](int kc, int s) {
        // B: staged smem image, linear copy
#pragma unroll
        for (int i = 0; i < 4; i++) {
            int task = tid + i * 512, n = task >> 3, seg = task & 7;
            cpa16(bU[s] + (uint32_t)(n * 128 + seg * 16),
                  g_Bw + ((kc * 256 + n) * 32 + seg * 4));
        }
        if (kc < 8) {  // A: gathered src/dst embeddings
#pragma unroll
            for (int i = 0; i < 2; i++) {
                int task = tid + i * 512, row = task >> 3, seg = task & 7;
                const float* p = (kc < 4 ? srcP[row] : dstP[row]) + (kc & 3) * 32;
                cpa16(aU[s] + (uint32_t)((row * LD + seg * 4) * 4), p + seg * 4);
            }
        } else {       // A: a1 = relu(feat @ W1^T + b1) on the fly
            float* A = Asp[s];
#pragma unroll
            for (int i = 0; i < 8; i++) {
                int task = tid + i * 512, e = task >> 5, c = task & 31;
                int j = (kc - 8) * 32 + c;
                float2 wv = w1s[j];
                A[e * LD + c] = fmaxf(tsA[e] * wv.x + wlA[e] * wv.y + b1s[j], 0.0f);
            }
        }
    };

    float acc[2][8][4];
#pragma unroll
    for (int mt = 0; mt < 2; mt++)
#pragma unroll
        for (int nt = 0; nt < 8; nt++)
#pragma unroll
            for (int r = 0; r < 4; r++) acc[mt][nt][r] = 0.0f;

    load_chunk(0, 0); CP_COMMIT();
    load_chunk(1, 1); CP_COMMIT();
    for (int kc = 0; kc < 16; kc++) {
        int s = kc % 3;
        if (kc == 15) { CP_WAIT(0); } else { CP_WAIT(1); }
        __syncthreads();
        if (kc < 14) { load_chunk(kc + 2, (kc + 2) % 3); CP_COMMIT(); }
        mma_chunk(Asp[s], bU[s], wm, wn, g, t, acc);
    }

    // epilogue: +relb2[rel], relu, mask, mean over each 16-row node group
#pragma unroll
    for (int mt = 0; mt < 2; mt++) {
        int mrow0 = wm * 32 + mt * 16;
        int eg = mrow0 + g, eg8 = eg + 8;
        float vg = vmA[eg], vg8 = vmA[eg8];
        const float* rbg  = rb + relA[eg] * 256;
        const float* rbg8 = rb + relA[eg8] * 256;
        int node = blockIdx.x * 8 + wm * 2 + mt;
#pragma unroll
        for (int nt = 0; nt < 8; nt++) {
            int col = wn * 64 + nt * 8 + t * 2;
            float s0 = fmaxf(acc[mt][nt][0] + rbg[col], 0.0f) * vg
                     + fmaxf(acc[mt][nt][2] + rbg8[col], 0.0f) * vg8;
            float s1 = fmaxf(acc[mt][nt][1] + rbg[col + 1], 0.0f) * vg
                     + fmaxf(acc[mt][nt][3] + rbg8[col + 1], 0.0f) * vg8;
            s0 += __shfl_xor_sync(0xFFFFFFFFu, s0, 4);
            s0 += __shfl_xor_sync(0xFFFFFFFFu, s0, 8);
            s0 += __shfl_xor_sync(0xFFFFFFFFu, s0, 16);
            s1 += __shfl_xor_sync(0xFFFFFFFFu, s1, 4);
            s1 += __shfl_xor_sync(0xFFFFFFFFu, s1, 8);
            s1 += __shfl_xor_sync(0xFFFFFFFFu, s1, 16);
            if (g == 0)
                *(float2*)(g_neigh + node * 256 + col) =
                    make_float2(s0 * 0.0625f, s1 * 0.0625f);
        }
    }
}

// ---------------- kernel 3: out = relu(self_e @ Wself^T + neigh @ Wneigh^T) ----------------
__global__ void __launch_bounds__(512) k_final(
    const int* __restrict__ node_ids, const float* __restrict__ emb0,
    float* __restrict__ out)
{
    float* Bsb  = smf;
    float* Asb  = smf + 3 * B2_F;
    float* meta = smf + 3 * B2_F + 3 * A_F;
    const float** selfP = (const float**)meta;  // 128 ptrs

    const int tid = threadIdx.x;
    const int wid = tid >> 5, lane = tid & 31;
    const int wm = wid >> 2, wn = wid & 3;
    const int g = lane >> 2, t = lane & 3;

    if (tid < 128) {
        long nid = node_ids[blockIdx.x * 128 + tid];
        selfP[tid] = emb0 + nid * EMB;
    }
    __syncthreads();

    uint32_t bU[3]; float* Asp[3]; uint32_t aU[3];
#pragma unroll
    for (int s = 0; s < 3; s++) {
        bU[s]  = smaddr(Bsb + s * B2_F);
        Asp[s] = Asb + s * A_F;
        aU[s]  = smaddr(Asp[s]);
    }

    auto load_chunk = [&](int kc, int s) {
#pragma unroll
        for (int i = 0; i < 4; i++) {
            int task = tid + i * 512, n = task >> 3, seg = task & 7;
            cpa16(bU[s] + (uint32_t)(n * 128 + seg * 16),
                  g_Bw2 + ((kc * 256 + n) * 32 + seg * 4));
        }
#pragma unroll
        for (int i = 0; i < 2; i++) {
            int task = tid + i * 512, row = task >> 3, seg = task & 7;
            const float* p;
            if (kc < 4) p = selfP[row] + kc * 32;
            else        p = g_neigh + (long)(blockIdx.x * 128 + row) * 256 + (kc - 4) * 32;
            cpa16(aU[s] + (uint32_t)((row * LD + seg * 4) * 4), p + seg * 4);
        }
    };

    float acc[2][8][4];
#pragma unroll
    for (int mt = 0; mt < 2; mt++)
#pragma unroll
        for (int nt = 0; nt < 8; nt++)
#pragma unroll
            for (int r = 0; r < 4; r++) acc[mt][nt][r] = 0.0f;

    load_chunk(0, 0); CP_COMMIT();
    load_chunk(1, 1); CP_COMMIT();
    for (int kc = 0; kc < 12; kc++) {
        int s = kc % 3;
        if (kc == 11) { CP_WAIT(0); } else { CP_WAIT(1); }
        __syncthreads();
        if (kc < 10) { load_chunk(kc + 2, (kc + 2) % 3); CP_COMMIT(); }
        mma_chunk(Asp[s], bU[s], wm, wn, g, t, acc);
    }

#pragma unroll
    for (int mt = 0; mt < 2; mt++) {
        int row0 = blockIdx.x * 128 + wm * 32 + mt * 16;
#pragma unroll
        for (int nt = 0; nt < 8; nt++) {
            int col = wn * 64 + nt * 8 + t * 2;
            *(float2*)(out + (long)(row0 + g) * 256 + col) =
                make_float2(fmaxf(acc[mt][nt][0], 0.0f), fmaxf(acc[mt][nt][1], 0.0f));
            *(float2*)(out + (long)(row0 + g + 8) * 256 + col) =
                make_float2(fmaxf(acc[mt][nt][2], 0.0f), fmaxf(acc[mt][nt][3], 0.0f));
        }
    }
}

static constexpr int SMEM2 = (3 * B2_F + 3 * A_F + 5888) * 4;  // 177152 B
static constexpr int SMEM3 = (3 * B2_F + 3 * A_F + 256) * 4;   // 154624 B

extern "C" void kernel_launch(void* const* d_in, const int* in_sizes, int n_in,
                              void* d_out, int out_size) {
    const int*   node_ids = (const int*)d_in[0];
    const int*   nbr_ev   = (const int*)d_in[1];
    const int*   ev_st    = (const int*)d_in[2];
    const int*   ev_dt    = (const int*)d_in[3];
    const int*   ev_et    = (const int*)d_in[4];
    const int*   ev_sid   = (const int*)d_in[5];
    const int*   ev_did   = (const int*)d_in[6];
    const int*   ev_ts    = (const int*)d_in[7];
    const float* ev_w     = (const float*)d_in[8];
    const float* emb0     = (const float*)d_in[9];
    const float* emb1     = (const float*)d_in[10];
    const float* edge_emb = (const float*)d_in[11];
    const float* edge_lin = (const float*)d_in[12];
    const float* mlp_w1   = (const float*)d_in[13];
    const float* mlp_b1   = (const float*)d_in[14];
    const float* mlp_w2   = (const float*)d_in[15];
    const float* mlp_b2   = (const float*)d_in[16];
    const float* ev_src_w = (const float*)d_in[17];
    const float* ev_dst_w = (const float*)d_in[18];
    const float* self_w   = (const float*)d_in[19];
    const float* neigh_w  = (const float*)d_in[20];
    float* out = (float*)d_out;

    cudaFuncSetAttribute(k_events, cudaFuncAttributeMaxDynamicSharedMemorySize, SMEM2);
    cudaFuncSetAttribute(k_final,  cudaFuncAttributeMaxDynamicSharedMemorySize, SMEM3);

    k_prep<<<896, 256>>>(ev_src_w, ev_dst_w, mlp_w2, self_w, neigh_w);
    k_relproj<<<16, 256>>>(edge_emb, edge_lin, mlp_b2);
    k_events<<<BE / 128, 512, SMEM2>>>(nbr_ev, ev_st, ev_dt, ev_et, ev_sid, ev_did,
                                       ev_ts, ev_w, emb0, emb1, mlp_w1, mlp_b1);
    k_final<<<BN / 128, 512, SMEM3>>>(node_ids, emb0, out);
}

// round 5
// speedup vs baseline: 1.1446x; 1.0162x over previous
#include <cuda_runtime.h>
#include <cstdint>
#include <math.h>

#define DEVI __device__ __forceinline__

static constexpr int BN = 16384, FAN = 16, BE = BN * FAN, EMB = 128, HID = 256;

// ---- device scratch (static; no allocations allowed) ----
__device__ __align__(16) float g_relb2[16 * HID];
__device__ __align__(16) float g_neigh[BN * HID];
__device__ __align__(16) float g_Bw [16 * 256 * 32];  // k_events B: tf32, permuted+swizzled smem image
__device__ __align__(16) float g_Bw2[12 * 256 * 32];  // k_final  B: same

DEVI uint32_t smaddr(const void* p) {
    uint32_t a;
    asm("{ .reg .u64 t; cvta.to.shared.u64 t, %1; cvt.u32.u64 %0, t; }" : "=r"(a) : "l"(p));
    return a;
}
DEVI void cpa16(uint32_t d, const void* s) {
    asm volatile("cp.async.ca.shared.global [%0], [%1], 16;" :: "r"(d), "l"(s));
}
#define CP_COMMIT() asm volatile("cp.async.commit_group;")
#define CP_WAIT(n)  asm volatile("cp.async.wait_group %0;" :: "n"(n))

DEVI uint32_t tf32u(float x) {
    uint32_t u;
    asm("cvt.rna.tf32.f32 %0, %1;" : "=r"(u) : "f"(x));
    return u;
}
DEVI float tf32f(float x) { return __uint_as_float(tf32u(x)); }

DEVI void lds64(uint32_t& x, uint32_t& y, uint32_t a) {
    asm volatile("ld.shared.v2.b32 {%0,%1}, [%2];" : "=r"(x), "=r"(y) : "r"(a));
}
DEVI void mma8(float* c, const uint32_t* a, uint32_t b0, uint32_t b1) {
    asm volatile(
        "mma.sync.aligned.m16n8k8.row.col.f32.tf32.tf32.f32 "
        "{%0,%1,%2,%3}, {%4,%5,%6,%7}, {%8,%9}, {%0,%1,%2,%3};"
        : "+f"(c[0]), "+f"(c[1]), "+f"(c[2]), "+f"(c[3])
        : "r"(a[0]), "r"(a[1]), "r"(a[2]), "r"(a[3]), "r"(b0), "r"(b1));
}

static constexpr int LD   = 36;        // A smem row stride (floats), padded
static constexpr int A_F  = 128 * LD;  // 4608 floats / A stage
static constexpr int B2_F = 256 * 32;  // 8192 floats / B stage (dense 128B rows)

// ---- B staging: logical W[r][k] (k within 32-chunk) -> smem-image position ----
// pair-permute within each k8 group: j -> p = 2*(j&3)+(j>>2)  (puts k=t,t+4 adjacent)
// XOR-swizzle 16B chunks: c -> c ^ ((r&3)<<1)                 (conflict-free phases)
DEVI void stash(float* dst, int r, int k, float v) {
    int kg = k >> 3, j = k & 7;
    int pos = kg * 8 + 2 * (j & 3) + (j >> 2);
    int cc  = (pos >> 2) ^ ((r & 3) << 1);
    dst[r * 32 + cc * 4 + (pos & 3)] = __uint_as_float(tf32u(v));
}

// ---- one K=32 chunk of warp-tiled MMA; CTA 128x256, 16 warps, warp tile 32x64 ----
// A is consumed as raw fp32 bits (tf32 HW truncation); B image is pre-rounded (rna).
DEVI void mma_chunk(const float* As, uint32_t bB, int wm, int wn, int g, int t,
                    float (&acc)[2][8][4]) {
    const uint32_t sw = (uint32_t)((g & 3) << 1);
    uint32_t nbase[8];
#pragma unroll
    for (int nt = 0; nt < 8; nt++)
        nbase[nt] = bB + (uint32_t)((wn * 64 + nt * 8 + g) * 128) + ((t & 1) << 3);
#pragma unroll
    for (int ks = 0; ks < 4; ks++) {
        // ---- batch A fragment loads (raw bits, no CVT) ----
        uint32_t a[2][4];
#pragma unroll
        for (int mt = 0; mt < 2; mt++) {
            const float* r0 = As + (wm * 32 + mt * 16 + g) * LD + ks * 8;
            const float* r8 = r0 + 8 * LD;
            a[mt][0] = __float_as_uint(r0[t]);
            a[mt][1] = __float_as_uint(r8[t]);
            a[mt][2] = __float_as_uint(r0[t + 4]);
            a[mt][3] = __float_as_uint(r8[t + 4]);
        }
        // ---- batch B fragment loads ----
        const uint32_t cc = (((uint32_t)(ks * 2 + (t >> 1))) ^ sw) << 4;
        uint32_t b[8][2];
#pragma unroll
        for (int nt = 0; nt < 8; nt++)
            lds64(b[nt][0], b[nt][1], nbase[nt] + cc);
        // ---- 16 back-to-back MMAs ----
#pragma unroll
        for (int nt = 0; nt < 8; nt++) {
            mma8(acc[0][nt], a[0], b[nt][0], b[nt][1]);
            mma8(acc[1][nt], a[1], b[nt][0], b[nt][1]);
        }
    }
}

// ---------------- kernel 0: stage weights (tf32 + permute + swizzle) ----------------
__global__ void k_prep(const float* __restrict__ Ws, const float* __restrict__ Wd,
                       const float* __restrict__ W2, const float* __restrict__ Wself,
                       const float* __restrict__ Wneigh) {
    int flat = blockIdx.x * 256 + threadIdx.x;
    if (flat < 16 * 8192) {
        int chunk = flat >> 13, r = (flat >> 5) & 255, k = flat & 31;
        float v;
        if (chunk < 4)      v = Ws[r * 128 + chunk * 32 + k];
        else if (chunk < 8) v = Wd[r * 128 + (chunk - 4) * 32 + k];
        else                v = W2[r * 256 + (chunk - 8) * 32 + k];
        stash(g_Bw + chunk * 8192, r, k, v);
    } else {
        int f = flat - 16 * 8192;
        int chunk = f >> 13, r = (f >> 5) & 255, k = f & 31;
        float v = (chunk < 4) ? Wself[r * 128 + chunk * 32 + k]
                              : Wneigh[r * 256 + (chunk - 4) * 32 + k];
        stash(g_Bw2 + chunk * 8192, r, k, v);
    }
}

// ---------------- kernel 1: relb2[r][j] = b2[j] + edge_emb[r] . edge_lin_w[j] ----------------
__global__ void k_relproj(const float* __restrict__ eemb, const float* __restrict__ We,
                          const float* __restrict__ b2) {
    int r = blockIdx.x, j = threadIdx.x;
    const float4* e = (const float4*)(eemb + r * EMB);
    const float4* w = (const float4*)(We + (long)j * EMB);
    float acc = b2[j];
#pragma unroll
    for (int k = 0; k < EMB / 4; k++) {
        float4 a = e[k], b = w[k];
        acc += a.x * b.x + a.y * b.y + a.z * b.z + a.w * b.w;
    }
    g_relb2[r * HID + j] = acc;
}

// ---------------- kernel 2: event GEMM [BE,512]x[512,256] -> mask/relu -> mean ----------------
extern __shared__ float smf[];

__global__ void __launch_bounds__(512) k_events(
    const int* __restrict__ nbr_ev, const int* __restrict__ ev_st,
    const int* __restrict__ ev_dt, const int* __restrict__ ev_et,
    const int* __restrict__ ev_sid, const int* __restrict__ ev_did,
    const int* __restrict__ ev_ts, const float* __restrict__ ev_w,
    const float* __restrict__ emb0, const float* __restrict__ emb1,
    const float* __restrict__ w1, const float* __restrict__ b1v)
{
    float* Bsb  = smf;                       // 3 x B2_F
    float* Asb  = smf + 3 * B2_F;            // 3 x A_F
    float* meta = smf + 3 * B2_F + 3 * A_F;
    const float** srcP = (const float**)meta;           // 128 ptrs (256 f)
    const float** dstP = (const float**)(meta + 256);   // 128 ptrs
    int*   relA = (int*)(meta + 512);
    float* vmA  = meta + 640;
    float* tsA  = meta + 768;
    float* wlA  = meta + 896;
    float* rb   = meta + 1024;                          // 16x256
    float2* w1s = (float2*)(meta + 5120);               // 256
    float* b1s  = meta + 5632;                          // 256

    const int tid = threadIdx.x;
    const int wid = tid >> 5, lane = tid & 31;
    const int wm = wid >> 2, wn = wid & 3;
    const int g = lane >> 2, t = lane & 3;

    if (tid < 128) {
        int e   = blockIdx.x * 128 + tid;
        int raw = nbr_ev[e];
        int v   = raw >= 0;
        int ev  = v ? raw : 0;
        long sid = ev_sid[ev], did = ev_did[ev];
        srcP[tid] = (ev_st[ev] == 0 ? emb0 : emb1) + sid * EMB;
        dstP[tid] = (ev_dt[ev] == 0 ? emb0 : emb1) + did * EMB;
        relA[tid] = ev_et[ev];
        vmA[tid]  = v ? 1.0f : 0.0f;
        tsA[tid]  = (float)ev_ts[ev] / 1000000.0f;
        wlA[tid]  = log1pf(ev_w[ev]);
    }
#pragma unroll
    for (int i = 0; i < 8; i++) rb[tid + i * 512] = g_relb2[tid + i * 512];
    if (tid < 256) {
        w1s[tid] = make_float2(w1[tid * 2], w1[tid * 2 + 1]);
        b1s[tid] = b1v[tid];
    }
    __syncthreads();

    uint32_t bU[3]; float* Asp[3]; uint32_t aU[3];
#pragma unroll
    for (int s = 0; s < 3; s++) {
        bU[s]  = smaddr(Bsb + s * B2_F);
        Asp[s] = Asb + s * A_F;
        aU[s]  = smaddr(Asp[s]);
    }

    auto load_chunk = [&](int kc, int s) {
        // B: staged smem image, linear copy
#pragma unroll
        for (int i = 0; i < 4; i++) {
            int task = tid + i * 512, n = task >> 3, seg = task & 7;
            cpa16(bU[s] + (uint32_t)(n * 128 + seg * 16),
                  g_Bw + ((kc * 256 + n) * 32 + seg * 4));
        }
        if (kc < 8) {  // A: gathered src/dst embeddings
#pragma unroll
            for (int i = 0; i < 2; i++) {
                int task = tid + i * 512, row = task >> 3, seg = task & 7;
                const float* p = (kc < 4 ? srcP[row] : dstP[row]) + (kc & 3) * 32;
                cpa16(aU[s] + (uint32_t)((row * LD + seg * 4) * 4), p + seg * 4);
            }
        } else {       // A: a1 = relu(feat @ W1^T + b1), rna-rounded at store
            float* A = Asp[s];
#pragma unroll
            for (int i = 0; i < 8; i++) {
                int task = tid + i * 512, e = task >> 5, c = task & 31;
                int j = (kc - 8) * 32 + c;
                float2 wv = w1s[j];
                A[e * LD + c] = tf32f(fmaxf(tsA[e] * wv.x + wlA[e] * wv.y + b1s[j], 0.0f));
            }
        }
    };

    float acc[2][8][4];
#pragma unroll
    for (int mt = 0; mt < 2; mt++)
#pragma unroll
        for (int nt = 0; nt < 8; nt++)
#pragma unroll
            for (int r = 0; r < 4; r++) acc[mt][nt][r] = 0.0f;

    load_chunk(0, 0); CP_COMMIT();
    load_chunk(1, 1); CP_COMMIT();
    for (int kc = 0; kc < 16; kc++) {
        int s = kc % 3;
        if (kc == 15) { CP_WAIT(0); } else { CP_WAIT(1); }
        __syncthreads();
        if (kc < 14) { load_chunk(kc + 2, (kc + 2) % 3); CP_COMMIT(); }
        mma_chunk(Asp[s], bU[s], wm, wn, g, t, acc);
    }

    // epilogue: +relb2[rel], relu, mask, mean over each 16-row node group
#pragma unroll
    for (int mt = 0; mt < 2; mt++) {
        int mrow0 = wm * 32 + mt * 16;
        int eg = mrow0 + g, eg8 = eg + 8;
        float vg = vmA[eg], vg8 = vmA[eg8];
        const float* rbg  = rb + relA[eg] * 256;
        const float* rbg8 = rb + relA[eg8] * 256;
        int node = blockIdx.x * 8 + wm * 2 + mt;
#pragma unroll
        for (int nt = 0; nt < 8; nt++) {
            int col = wn * 64 + nt * 8 + t * 2;
            float s0 = fmaxf(acc[mt][nt][0] + rbg[col], 0.0f) * vg
                     + fmaxf(acc[mt][nt][2] + rbg8[col], 0.0f) * vg8;
            float s1 = fmaxf(acc[mt][nt][1] + rbg[col + 1], 0.0f) * vg
                     + fmaxf(acc[mt][nt][3] + rbg8[col + 1], 0.0f) * vg8;
            s0 += __shfl_xor_sync(0xFFFFFFFFu, s0, 4);
            s0 += __shfl_xor_sync(0xFFFFFFFFu, s0, 8);
            s0 += __shfl_xor_sync(0xFFFFFFFFu, s0, 16);
            s1 += __shfl_xor_sync(0xFFFFFFFFu, s1, 4);
            s1 += __shfl_xor_sync(0xFFFFFFFFu, s1, 8);
            s1 += __shfl_xor_sync(0xFFFFFFFFu, s1, 16);
            if (g == 0)
                *(float2*)(g_neigh + node * 256 + col) =
                    make_float2(s0 * 0.0625f, s1 * 0.0625f);
        }
    }
}

// ---------------- kernel 3: out = relu(self_e @ Wself^T + neigh @ Wneigh^T) ----------------
__global__ void __launch_bounds__(512) k_final(
    const int* __restrict__ node_ids, const float* __restrict__ emb0,
    float* __restrict__ out)
{
    float* Bsb  = smf;
    float* Asb  = smf + 3 * B2_F;
    float* meta = smf + 3 * B2_F + 3 * A_F;
    const float** selfP = (const float**)meta;  // 128 ptrs

    const int tid = threadIdx.x;
    const int wid = tid >> 5, lane = tid & 31;
    const int wm = wid >> 2, wn = wid & 3;
    const int g = lane >> 2, t = lane & 3;

    if (tid < 128) {
        long nid = node_ids[blockIdx.x * 128 + tid];
        selfP[tid] = emb0 + nid * EMB;
    }
    __syncthreads();

    uint32_t bU[3]; float* Asp[3]; uint32_t aU[3];
#pragma unroll
    for (int s = 0; s < 3; s++) {
        bU[s]  = smaddr(Bsb + s * B2_F);
        Asp[s] = Asb + s * A_F;
        aU[s]  = smaddr(Asp[s]);
    }

    auto load_chunk = [&](int kc, int s) {
#pragma unroll
        for (int i = 0; i < 4; i++) {
            int task = tid + i * 512, n = task >> 3, seg = task & 7;
            cpa16(bU[s] + (uint32_t)(n * 128 + seg * 16),
                  g_Bw2 + ((kc * 256 + n) * 32 + seg * 4));
        }
#pragma unroll
        for (int i = 0; i < 2; i++) {
            int task = tid + i * 512, row = task >> 3, seg = task & 7;
            const float* p;
            if (kc < 4) p = selfP[row] + kc * 32;
            else        p = g_neigh + (long)(blockIdx.x * 128 + row) * 256 + (kc - 4) * 32;
            cpa16(aU[s] + (uint32_t)((row * LD + seg * 4) * 4), p + seg * 4);
        }
    };

    float acc[2][8][4];
#pragma unroll
    for (int mt = 0; mt < 2; mt++)
#pragma unroll
        for (int nt = 0; nt < 8; nt++)
#pragma unroll
            for (int r = 0; r < 4; r++) acc[mt][nt][r] = 0.0f;

    load_chunk(0, 0); CP_COMMIT();
    load_chunk(1, 1); CP_COMMIT();
    for (int kc = 0; kc < 12; kc++) {
        int s = kc % 3;
        if (kc == 11) { CP_WAIT(0); } else { CP_WAIT(1); }
        __syncthreads();
        if (kc < 10) { load_chunk(kc + 2, (kc + 2) % 3); CP_COMMIT(); }
        mma_chunk(Asp[s], bU[s], wm, wn, g, t, acc);
    }

#pragma unroll
    for (int mt = 0; mt < 2; mt++) {
        int row0 = blockIdx.x * 128 + wm * 32 + mt * 16;
#pragma unroll
        for (int nt = 0; nt < 8; nt++) {
            int col = wn * 64 + nt * 8 + t * 2;
            *(float2*)(out + (long)(row0 + g) * 256 + col) =
                make_float2(fmaxf(acc[mt][nt][0], 0.0f), fmaxf(acc[mt][nt][1], 0.0f));
            *(float2*)(out + (long)(row0 + g + 8) * 256 + col) =
                make_float2(fmaxf(acc[mt][nt][2], 0.0f), fmaxf(acc[mt][nt][3], 0.0f));
        }
    }
}

static constexpr int SMEM2 = (3 * B2_F + 3 * A_F + 5888) * 4;  // 177152 B
static constexpr int SMEM3 = (3 * B2_F + 3 * A_F + 256) * 4;   // 154624 B

extern "C" void kernel_launch(void* const* d_in, const int* in_sizes, int n_in,
                              void* d_out, int out_size) {
    const int*   node_ids = (const int*)d_in[0];
    const int*   nbr_ev   = (const int*)d_in[1];
    const int*   ev_st    = (const int*)d_in[2];
    const int*   ev_dt    = (const int*)d_in[3];
    const int*   ev_et    = (const int*)d_in[4];
    const int*   ev_sid   = (const int*)d_in[5];
    const int*   ev_did   = (const int*)d_in[6];
    const int*   ev_ts    = (const int*)d_in[7];
    const float* ev_w     = (const float*)d_in[8];
    const float* emb0     = (const float*)d_in[9];
    const float* emb1     = (const float*)d_in[10];
    const float* edge_emb = (const float*)d_in[11];
    const float* edge_lin = (const float*)d_in[12];
    const float* mlp_w1   = (const float*)d_in[13];
    const float* mlp_b1   = (const float*)d_in[14];
    const float* mlp_w2   = (const float*)d_in[15];
    const float* mlp_b2   = (const float*)d_in[16];
    const float* ev_src_w = (const float*)d_in[17];
    const float* ev_dst_w = (const float*)d_in[18];
    const float* self_w   = (const float*)d_in[19];
    const float* neigh_w  = (const float*)d_in[20];
    float* out = (float*)d_out;

    cudaFuncSetAttribute(k_events, cudaFuncAttributeMaxDynamicSharedMemorySize, SMEM2);
    cudaFuncSetAttribute(k_final,  cudaFuncAttributeMaxDynamicSharedMemorySize, SMEM3);

    k_prep<<<896, 256>>>(ev_src_w, ev_dst_w, mlp_w2, self_w, neigh_w);
    k_relproj<<<16, 256>>>(edge_emb, edge_lin, mlp_b2);
    k_events<<<BE / 128, 512, SMEM2>>>(nbr_ev, ev_st, ev_dt, ev_et, ev_sid, ev_did,
                                       ev_ts, ev_w, emb0, emb1, mlp_w1, mlp_b1);
    k_final<<<BN / 128, 512, SMEM3>>>(node_ids, emb0, out);
}